// round 1
// baseline (speedup 1.0000x reference)
#include <cuda_runtime.h>
#include <math.h>

#define NVIEW 5
#define NBINS 128000
#define BATCH 2
#define HF 128
#define WF 128
#define HWF (HF*WF)
#define HI 512
#define WI 512
#define HWI (HI*WI)
#define CF 32
#define NCH 35          // 3 img + 32 feat channels
#define HID 256
#define INDIM 73
#define ROWP 76         // padded input row (19 float4)
#define MTOT (BATCH*NBINS)   // 256000

// ---------------- scratch (device globals: allocation-free) ----------------
__device__ float4 g_imgs_t[NVIEW*BATCH*HWI];            // [vb][p] = (r,g,b,0)   41.9MB
__device__ float4 g_feats_t[NVIEW*BATCH*HWF*(CF/4)];    // [vb][p][c]            41.9MB
__device__ float4 g_inp[MTOT*(ROWP/4)];                 // [m][76 floats]        77.8MB

// ---------------- packed fp32x2 FMA (Blackwell FFMA2) ----------------
__device__ __forceinline__ unsigned long long ffma2(unsigned long long a,
                                                    unsigned long long b,
                                                    unsigned long long c) {
    unsigned long long d;
    asm("fma.rn.f32x2 %0, %1, %2, %3;" : "=l"(d) : "l"(a), "l"(b), "l"(c));
    return d;
}

// ---------------- kernel 1a: transpose images [v,b,3,HW] -> [vb,HW,4] ----------------
__global__ void transpose_imgs(const float* __restrict__ im) {
    int idx = blockIdx.x * blockDim.x + threadIdx.x;   // vb*HWI + p
    if (idx >= NVIEW*BATCH*HWI) return;
    int vb = idx >> 18;                                // /262144
    int p  = idx & (HWI - 1);
    const float* base = im + (size_t)vb * 3 * HWI + p;
    g_imgs_t[idx] = make_float4(base[0], base[HWI], base[2*HWI], 0.f);
}

// ---------------- kernel 1b: transpose feats [v,b,32,HW] -> [vb,HW,32] ----------------
__global__ void transpose_feats(const float* __restrict__ f) {
    __shared__ float tile[32][33];
    int vb = blockIdx.y;
    int p0 = blockIdx.x * 32;
    int tx = threadIdx.x, ty = threadIdx.y;
    tile[ty][tx] = f[((size_t)vb*CF + ty) * HWF + p0 + tx];
    __syncthreads();
    ((float*)g_feats_t)[((size_t)vb*HWF + p0 + ty) * CF + tx] = tile[tx][ty];
}

// ---------------- kernel 2: bilinear gather + mean/var + build MLP input ----------------
__global__ __launch_bounds__(128)
void gather_kernel(const float* __restrict__ grid, const float* __restrict__ pts) {
    int m = blockIdx.x * 128 + threadIdx.x;   // m = b*NBINS + n
    int b = m / NBINS;
    int n = m - b * NBINS;

    float s[NCH], ss[NCH];
#pragma unroll
    for (int c = 0; c < NCH; c++) { s[c] = 0.f; ss[c] = 0.f; }

#pragma unroll
    for (int v = 0; v < NVIEW; v++) {
        float gx = grid[(v*NBINS + n)*2 + 0];
        float gy = grid[(v*NBINS + n)*2 + 1];

        // ---- image sample (512x512, 3 ch packed in float4) ----
        {
            float fx = (gx + 1.f) * 0.5f * (float)(WI - 1);
            float fy = (gy + 1.f) * 0.5f * (float)(HI - 1);
            float x0f = floorf(fx), y0f = floorf(fy);
            float wx1 = fx - x0f, wy1 = fy - y0f;
            float wx0 = 1.f - wx1, wy0 = 1.f - wy1;
            int x0 = max(0, min((int)x0f, WI-1));
            int y0 = max(0, min((int)y0f, HI-1));
            int x1 = min(x0 + 1, WI-1);
            int y1 = min(y0 + 1, HI-1);
            float w00 = wx0*wy0, w01 = wx1*wy0, w10 = wx0*wy1, w11 = wx1*wy1;
            int base = (v*BATCH + b) * HWI;
            float4 p00 = g_imgs_t[base + y0*WI + x0];
            float4 p01 = g_imgs_t[base + y0*WI + x1];
            float4 p10 = g_imgs_t[base + y1*WI + x0];
            float4 p11 = g_imgs_t[base + y1*WI + x1];
            float r0 = w00*p00.x + w01*p01.x + w10*p10.x + w11*p11.x;
            float r1 = w00*p00.y + w01*p01.y + w10*p10.y + w11*p11.y;
            float r2 = w00*p00.z + w01*p01.z + w10*p10.z + w11*p11.z;
            s[0] += r0; ss[0] += r0*r0;
            s[1] += r1; ss[1] += r1*r1;
            s[2] += r2; ss[2] += r2*r2;
        }

        // ---- feature sample (128x128, 32 ch contiguous) ----
        {
            float fx = (gx + 1.f) * 0.5f * (float)(WF - 1);
            float fy = (gy + 1.f) * 0.5f * (float)(HF - 1);
            float x0f = floorf(fx), y0f = floorf(fy);
            float wx1 = fx - x0f, wy1 = fy - y0f;
            float wx0 = 1.f - wx1, wy0 = 1.f - wy1;
            int x0 = max(0, min((int)x0f, WF-1));
            int y0 = max(0, min((int)y0f, HF-1));
            int x1 = min(x0 + 1, WF-1);
            int y1 = min(y0 + 1, HF-1);
            float w00 = wx0*wy0, w01 = wx1*wy0, w10 = wx0*wy1, w11 = wx1*wy1;
            int base = (v*BATCH + b) * HWF;
            int b00 = (base + y0*WF + x0) * (CF/4);
            int b01 = (base + y0*WF + x1) * (CF/4);
            int b10 = (base + y1*WF + x0) * (CF/4);
            int b11 = (base + y1*WF + x1) * (CF/4);
#pragma unroll
            for (int c4 = 0; c4 < CF/4; c4++) {
                float4 q00 = g_feats_t[b00 + c4];
                float4 q01 = g_feats_t[b01 + c4];
                float4 q10 = g_feats_t[b10 + c4];
                float4 q11 = g_feats_t[b11 + c4];
                int c = 3 + c4*4;
                float t;
                t = w00*q00.x + w01*q01.x + w10*q10.x + w11*q11.x; s[c+0]+=t; ss[c+0]+=t*t;
                t = w00*q00.y + w01*q01.y + w10*q10.y + w11*q11.y; s[c+1]+=t; ss[c+1]+=t*t;
                t = w00*q00.z + w01*q01.z + w10*q10.z + w11*q11.z; s[c+2]+=t; ss[c+2]+=t*t;
                t = w00*q00.w + w01*q01.w + w10*q10.w + w11*q11.w; s[c+3]+=t; ss[c+3]+=t*t;
            }
        }
    }

    // ---- finalize: inp row = [pts(3), mean(35), exp(-var)(35), pad(3)] ----
    float* o = ((float*)g_inp) + (size_t)m * ROWP;
    o[0] = pts[n*3 + 0];
    o[1] = pts[n*3 + 1];
    o[2] = pts[n*3 + 2];
#pragma unroll
    for (int c = 0; c < NCH; c++) {
        float mean = s[c] / 5.0f;
        float var  = fmaxf(ss[c] / 5.0f - mean * mean, 0.f);
        o[3 + c]       = mean;
        o[3 + NCH + c] = expf(-var);
    }
}

// ---------------- kernel 3: fused MLP  out = sigmoid(relu(x@W1+b1)@W2+b2) ----------------
// block: 128 threads = 16 (tx, hidden) x 8 (ty, points); 64 points x 256 hidden per block.
// Each thread: 8 points x 8 hidden-PAIRS (16 hidden) with packed f32x2 FMA.
#define SMEM_FLOATS (INDIM*HID + 64*77 + HID + HID)
#define SMEM_BYTES  (SMEM_FLOATS * 4)

__global__ __launch_bounds__(128, 2)
void mlp_kernel(const float* __restrict__ W1, const float* __restrict__ b1,
                const float* __restrict__ W2, const float* __restrict__ b2,
                float* __restrict__ out) {
    extern __shared__ float smf[];
    float* Ws  = smf;                 // [73][256]
    float* As  = smf + INDIM*HID;     // [64][77]  (stride 77 -> conflict-free x loads)
    float* b1s = As + 64*77;          // [256]
    float* w2s = b1s + HID;           // [256]

    int tid = threadIdx.x;

    // load W1 (73*256 floats) as float4
    const float4* W14 = (const float4*)W1;
#pragma unroll 1
    for (int i = tid; i < INDIM*HID/4; i += 128)
        ((float4*)Ws)[i] = W14[i];
    for (int i = tid; i < HID; i += 128) { b1s[i] = b1[i]; w2s[i] = W2[i]; }

    // load A tile: 64 rows x 19 float4 (store at stride 77)
    const float4* A4 = g_inp + (size_t)blockIdx.x * 64 * (ROWP/4);
#pragma unroll 1
    for (int i = tid; i < 64*(ROWP/4); i += 128) {
        int r = i / (ROWP/4), c = i - r*(ROWP/4);
        float4 vv = A4[i];
        float* dst = &As[r*77 + c*4];
        dst[0] = vv.x; dst[1] = vv.y; dst[2] = vv.z; dst[3] = vv.w;
    }
    __syncthreads();

    int tx = tid & 15, ty = tid >> 4;
    unsigned long long acc[8][8];
#pragma unroll
    for (int mi = 0; mi < 8; mi++)
#pragma unroll
        for (int i = 0; i < 8; i++) acc[mi][i] = 0ull;

    const float* arow = &As[ty*8*77];

#pragma unroll 2
    for (int k = 0; k < INDIM; k++) {
        unsigned long long xp[8];
#pragma unroll
        for (int mi = 0; mi < 8; mi++) {
            unsigned int xi = __float_as_uint(arow[mi*77 + k]);
            asm("mov.b64 %0, {%1,%1};" : "=l"(xp[mi]) : "r"(xi));
        }
        unsigned long long wv[8];
        const float* wr = &Ws[k*HID + tx*2];
#pragma unroll
        for (int i = 0; i < 8; i++)
            wv[i] = *(const unsigned long long*)(wr + i*32);
#pragma unroll
        for (int mi = 0; mi < 8; mi++)
#pragma unroll
            for (int i = 0; i < 8; i++)
                acc[mi][i] = ffma2(xp[mi], wv[i], acc[mi][i]);
    }

    // epilogue: relu + W2 dot + warp reduce over the 16 tx lanes + sigmoid
    float b2v = b2[0];
#pragma unroll
    for (int mi = 0; mi < 8; mi++) {
        float z = 0.f;
#pragma unroll
        for (int i = 0; i < 8; i++) {
            int j0 = i*32 + tx*2;
            float a0 = __uint_as_float((unsigned int)(acc[mi][i] & 0xffffffffull));
            float a1 = __uint_as_float((unsigned int)(acc[mi][i] >> 32));
            float h0 = fmaxf(a0 + b1s[j0],     0.f);
            float h1 = fmaxf(a1 + b1s[j0 + 1], 0.f);
            z += h0 * w2s[j0] + h1 * w2s[j0 + 1];
        }
#pragma unroll
        for (int off = 8; off >= 1; off >>= 1)
            z += __shfl_xor_sync(0xffffffffu, z, off);
        if (tx == 0) {
            float zz = z + b2v;
            // 1 - exp(-softplus(zz)) == sigmoid(zz)
            out[blockIdx.x*64 + ty*8 + mi] = 1.f / (1.f + expf(-zz));
        }
    }
}

// ---------------- launch ----------------
extern "C" void kernel_launch(void* const* d_in, const int* in_sizes, int n_in,
                              void* d_out, int out_size) {
    const float* imgs  = (const float*)d_in[0];
    const float* feats = (const float*)d_in[1];
    const float* grid  = (const float*)d_in[2];
    const float* pts   = (const float*)d_in[3];
    const float* W1    = (const float*)d_in[4];
    const float* b1    = (const float*)d_in[5];
    const float* W2    = (const float*)d_in[6];
    const float* b2    = (const float*)d_in[7];
    float* out = (float*)d_out;

    cudaFuncSetAttribute(mlp_kernel, cudaFuncAttributeMaxDynamicSharedMemorySize, SMEM_BYTES);

    transpose_imgs<<<(NVIEW*BATCH*HWI + 255)/256, 256>>>(imgs);
    transpose_feats<<<dim3(HWF/32, NVIEW*BATCH), dim3(32, 32)>>>(feats);
    gather_kernel<<<MTOT/128, 128>>>(grid, pts);
    mlp_kernel<<<MTOT/64, 128, SMEM_BYTES>>>(W1, b1, W2, b2, out);
}

// round 2
// speedup vs baseline: 1.3855x; 1.3855x over previous
#include <cuda_runtime.h>
#include <math.h>

#define NVIEW 5
#define NBINS 128000
#define BATCH 2
#define HF 128
#define WF 128
#define HWF (HF*WF)
#define HI 512
#define WI 512
#define HWI (HI*WI)
#define CF 32
#define NCH 35          // 3 img + 32 feat channels
#define HID 256
#define INDIM 73
#define ROWP 76         // padded input row (19 float4)
#define MTOT (BATCH*NBINS)   // 256000

// ---------------- scratch (device globals: allocation-free) ----------------
__device__ float4 g_imgs_t[NVIEW*BATCH*HWI];            // [vb][p] = (r,g,b,0)
__device__ float4 g_feats_t[NVIEW*BATCH*HWF*(CF/4)];    // [vb][p][c]
__device__ float4 g_inp[MTOT*(ROWP/4)];                 // [m][76 floats]

// ---------------- packed fp32x2 FMA (Blackwell FFMA2) ----------------
__device__ __forceinline__ unsigned long long ffma2(unsigned long long a,
                                                    unsigned long long b,
                                                    unsigned long long c) {
    unsigned long long d;
    asm("fma.rn.f32x2 %0, %1, %2, %3;" : "=l"(d) : "l"(a), "l"(b), "l"(c));
    return d;
}

// ---------------- kernel 1a: transpose images [v,b,3,HW] -> [vb,HW,4] ----------------
__global__ void transpose_imgs(const float* __restrict__ im) {
    int idx = blockIdx.x * blockDim.x + threadIdx.x;   // vb*HWI + p
    if (idx >= NVIEW*BATCH*HWI) return;
    int vb = idx >> 18;                                // /262144
    int p  = idx & (HWI - 1);
    const float* base = im + (size_t)vb * 3 * HWI + p;
    g_imgs_t[idx] = make_float4(base[0], base[HWI], base[2*HWI], 0.f);
}

// ---------------- kernel 1b: transpose feats [v,b,32,HW] -> [vb,HW,32] ----------------
__global__ void transpose_feats(const float* __restrict__ f) {
    __shared__ float tile[32][33];
    int vb = blockIdx.y;
    int p0 = blockIdx.x * 32;
    int tx = threadIdx.x, ty = threadIdx.y;
    tile[ty][tx] = f[((size_t)vb*CF + ty) * HWF + p0 + tx];
    __syncthreads();
    ((float*)g_feats_t)[((size_t)vb*HWF + p0 + ty) * CF + tx] = tile[tx][ty];
}

// ---------------- kernel 2: bilinear gather + mean/var + build MLP input ----------------
// 2 threads per point: half 0 does img(3) + feat ch 0..15; half 1 does feat ch 16..31.
// Halves the accumulator registers -> ~2x resident warps for latency hiding.
__global__ __launch_bounds__(256)
void gather_kernel(const float* __restrict__ grid, const float* __restrict__ pts) {
    int tid  = blockIdx.x * 256 + threadIdx.x;
    int m    = tid >> 1;                 // point index (b*NBINS + n)
    int half = tid & 1;
    int b = m / NBINS;
    int n = m - b * NBINS;

    const int NC = 19;                   // half0 uses 19, half1 uses 16
    float s[NC], ss[NC];
#pragma unroll
    for (int c = 0; c < NC; c++) { s[c] = 0.f; ss[c] = 0.f; }

#pragma unroll
    for (int v = 0; v < NVIEW; v++) {
        float gx = grid[(v*NBINS + n)*2 + 0];
        float gy = grid[(v*NBINS + n)*2 + 1];

        // ---- image sample (only half 0) ----
        if (half == 0) {
            float fx = (gx + 1.f) * 0.5f * (float)(WI - 1);
            float fy = (gy + 1.f) * 0.5f * (float)(HI - 1);
            float x0f = floorf(fx), y0f = floorf(fy);
            float wx1 = fx - x0f, wy1 = fy - y0f;
            float wx0 = 1.f - wx1, wy0 = 1.f - wy1;
            int x0 = max(0, min((int)x0f, WI-1));
            int y0 = max(0, min((int)y0f, HI-1));
            int x1 = min(x0 + 1, WI-1);
            int y1 = min(y0 + 1, HI-1);
            float w00 = wx0*wy0, w01 = wx1*wy0, w10 = wx0*wy1, w11 = wx1*wy1;
            int base = (v*BATCH + b) * HWI;
            float4 p00 = g_imgs_t[base + y0*WI + x0];
            float4 p01 = g_imgs_t[base + y0*WI + x1];
            float4 p10 = g_imgs_t[base + y1*WI + x0];
            float4 p11 = g_imgs_t[base + y1*WI + x1];
            float r0 = w00*p00.x + w01*p01.x + w10*p10.x + w11*p11.x;
            float r1 = w00*p00.y + w01*p01.y + w10*p10.y + w11*p11.y;
            float r2 = w00*p00.z + w01*p01.z + w10*p10.z + w11*p11.z;
            s[16] += r0; ss[16] += r0*r0;
            s[17] += r1; ss[17] += r1*r1;
            s[18] += r2; ss[18] += r2*r2;
        }

        // ---- feature sample: 4 c4-groups per half ----
        {
            float fx = (gx + 1.f) * 0.5f * (float)(WF - 1);
            float fy = (gy + 1.f) * 0.5f * (float)(HF - 1);
            float x0f = floorf(fx), y0f = floorf(fy);
            float wx1 = fx - x0f, wy1 = fy - y0f;
            float wx0 = 1.f - wx1, wy0 = 1.f - wy1;
            int x0 = max(0, min((int)x0f, WF-1));
            int y0 = max(0, min((int)y0f, HF-1));
            int x1 = min(x0 + 1, WF-1);
            int y1 = min(y0 + 1, HF-1);
            float w00 = wx0*wy0, w01 = wx1*wy0, w10 = wx0*wy1, w11 = wx1*wy1;
            int base = (v*BATCH + b) * HWF;
            int c4base = half * 4;
            int b00 = (base + y0*WF + x0) * (CF/4) + c4base;
            int b01 = (base + y0*WF + x1) * (CF/4) + c4base;
            int b10 = (base + y1*WF + x0) * (CF/4) + c4base;
            int b11 = (base + y1*WF + x1) * (CF/4) + c4base;
#pragma unroll
            for (int c4 = 0; c4 < 4; c4++) {
                float4 q00 = g_feats_t[b00 + c4];
                float4 q01 = g_feats_t[b01 + c4];
                float4 q10 = g_feats_t[b10 + c4];
                float4 q11 = g_feats_t[b11 + c4];
                int c = c4*4;
                float t;
                t = w00*q00.x + w01*q01.x + w10*q10.x + w11*q11.x; s[c+0]+=t; ss[c+0]+=t*t;
                t = w00*q00.y + w01*q01.y + w10*q10.y + w11*q11.y; s[c+1]+=t; ss[c+1]+=t*t;
                t = w00*q00.z + w01*q01.z + w10*q10.z + w11*q11.z; s[c+2]+=t; ss[c+2]+=t*t;
                t = w00*q00.w + w01*q01.w + w10*q10.w + w11*q11.w; s[c+3]+=t; ss[c+3]+=t*t;
            }
        }
    }

    // ---- finalize: inp row = [pts(3), mean(35), exp(-var)(35), pad(3)] ----
    float* o = ((float*)g_inp) + (size_t)m * ROWP;
    if (half == 0) {
        o[0] = pts[n*3 + 0];
        o[1] = pts[n*3 + 1];
        o[2] = pts[n*3 + 2];
        // img channels -> global ch 0..2 (stored in s[16..18])
#pragma unroll
        for (int c = 0; c < 3; c++) {
            float mean = s[16+c] * 0.2f;
            float var  = fmaxf(ss[16+c] * 0.2f - mean*mean, 0.f);
            o[3 + c]       = mean;
            o[3 + NCH + c] = expf(-var);
        }
        // feat ch 0..15 -> global ch 3..18
#pragma unroll
        for (int c = 0; c < 16; c++) {
            float mean = s[c] * 0.2f;
            float var  = fmaxf(ss[c] * 0.2f - mean*mean, 0.f);
            o[3 + 3 + c]       = mean;
            o[3 + NCH + 3 + c] = expf(-var);
        }
    } else {
        // feat ch 16..31 -> global ch 19..34
#pragma unroll
        for (int c = 0; c < 16; c++) {
            float mean = s[c] * 0.2f;
            float var  = fmaxf(ss[c] * 0.2f - mean*mean, 0.f);
            o[3 + 19 + c]       = mean;
            o[3 + NCH + 19 + c] = expf(-var);
        }
        o[73] = 0.f; o[74] = 0.f; o[75] = 0.f;   // pad
    }
}

// ---------------- kernel 3: fused MLP  out = sigmoid(relu(x@W1+b1)@W2+b2) ----------------
// 256 threads = 32 (tx, hidden) x 8 (warps/points). 64 points x 256 hidden per block.
// Each thread: 8 points x 4 hidden-pairs (8 hidden) with packed f32x2 FMA.
// acc = 32 ull = 64 regs -> ~110 regs/thread -> 2 blocks/SM (16 warps, occ 25%).
#define SMEM_FLOATS (INDIM*HID + 64*ROWP + HID + HID)
#define SMEM_BYTES  (SMEM_FLOATS * 4)

__global__ __launch_bounds__(256, 2)
void mlp_kernel(const float* __restrict__ W1, const float* __restrict__ b1,
                const float* __restrict__ W2, const float* __restrict__ b2,
                float* __restrict__ out) {
    extern __shared__ float smf[];
    float* Ws  = smf;                    // [73][256]
    float* As  = smf + INDIM*HID;        // [64][76]
    float* b1s = As + 64*ROWP;           // [256]
    float* w2s = b1s + HID;              // [256]

    int tid = threadIdx.x;

    // load W1 (73*256 floats) as float4
    const float4* W14 = (const float4*)W1;
#pragma unroll 1
    for (int i = tid; i < INDIM*HID/4; i += 256)
        ((float4*)Ws)[i] = W14[i];
    if (tid < HID) { b1s[tid] = b1[tid]; w2s[tid] = W2[tid]; }

    // load A tile: 64 rows x 19 float4
    const float4* A4 = g_inp + (size_t)blockIdx.x * 64 * (ROWP/4);
#pragma unroll 1
    for (int i = tid; i < 64*(ROWP/4); i += 256) {
        int r = i / (ROWP/4), c = i - r*(ROWP/4);
        float4 vv = A4[i];
        float* dst = &As[r*ROWP + c*4];
        dst[0] = vv.x; dst[1] = vv.y; dst[2] = vv.z; dst[3] = vv.w;
    }
    __syncthreads();

    int tx = tid & 31, ty = tid >> 5;    // ty = warp id; warp owns points ty*8..ty*8+7
    unsigned long long acc[8][4];
#pragma unroll
    for (int mi = 0; mi < 8; mi++)
#pragma unroll
        for (int i = 0; i < 4; i++) acc[mi][i] = 0ull;

    const float* arow = &As[ty*8*ROWP];

#pragma unroll 2
    for (int k = 0; k < INDIM; k++) {
        unsigned long long xp[8];
#pragma unroll
        for (int mi = 0; mi < 8; mi++) {
            unsigned int xi = __float_as_uint(arow[mi*ROWP + k]);   // warp-broadcast
            asm("mov.b64 %0, {%1,%1};" : "=l"(xp[mi]) : "r"(xi));
        }
        unsigned long long wv[4];
        const float* wr = &Ws[k*HID + tx*2];
#pragma unroll
        for (int i = 0; i < 4; i++)
            wv[i] = *(const unsigned long long*)(wr + i*64);
#pragma unroll
        for (int mi = 0; mi < 8; mi++)
#pragma unroll
            for (int i = 0; i < 4; i++)
                acc[mi][i] = ffma2(xp[mi], wv[i], acc[mi][i]);
    }

    // epilogue: relu + W2 dot + full-warp reduce + sigmoid
    float b2v = b2[0];
#pragma unroll
    for (int mi = 0; mi < 8; mi++) {
        float z = 0.f;
#pragma unroll
        for (int i = 0; i < 4; i++) {
            int j0 = i*64 + tx*2;
            float a0 = __uint_as_float((unsigned int)(acc[mi][i] & 0xffffffffull));
            float a1 = __uint_as_float((unsigned int)(acc[mi][i] >> 32));
            float h0 = fmaxf(a0 + b1s[j0],     0.f);
            float h1 = fmaxf(a1 + b1s[j0 + 1], 0.f);
            z += h0 * w2s[j0] + h1 * w2s[j0 + 1];
        }
#pragma unroll
        for (int off = 16; off >= 1; off >>= 1)
            z += __shfl_xor_sync(0xffffffffu, z, off);
        if (tx == 0) {
            float zz = z + b2v;
            // 1 - exp(-softplus(zz)) == sigmoid(zz)
            out[blockIdx.x*64 + ty*8 + mi] = 1.f / (1.f + expf(-zz));
        }
    }
}

// ---------------- launch ----------------
extern "C" void kernel_launch(void* const* d_in, const int* in_sizes, int n_in,
                              void* d_out, int out_size) {
    const float* imgs  = (const float*)d_in[0];
    const float* feats = (const float*)d_in[1];
    const float* grid  = (const float*)d_in[2];
    const float* pts   = (const float*)d_in[3];
    const float* W1    = (const float*)d_in[4];
    const float* b1    = (const float*)d_in[5];
    const float* W2    = (const float*)d_in[6];
    const float* b2    = (const float*)d_in[7];
    float* out = (float*)d_out;

    cudaFuncSetAttribute(mlp_kernel, cudaFuncAttributeMaxDynamicSharedMemorySize, SMEM_BYTES);

    transpose_imgs<<<(NVIEW*BATCH*HWI + 255)/256, 256>>>(imgs);
    transpose_feats<<<dim3(HWF/32, NVIEW*BATCH), dim3(32, 32)>>>(feats);
    gather_kernel<<<(2*MTOT)/256, 256>>>(grid, pts);
    mlp_kernel<<<MTOT/64, 256, SMEM_BYTES>>>(W1, b1, W2, b2, out);
}

// round 3
// speedup vs baseline: 1.7152x; 1.2379x over previous
#include <cuda_runtime.h>
#include <math.h>

#define NVIEW 5
#define NBINS 128000
#define BATCH 2
#define HF 128
#define WF 128
#define HWF (HF*WF)
#define HI 512
#define WI 512
#define HWI (HI*WI)
#define CF 32
#define NCH 35            // 3 img + 32 feat channels
#define HID 256
#define INDIM 73
#define KPAD 76           // padded K (19 x 4)
#define MTOT (BATCH*NBINS)   // 256000

// ---------------- scratch (device globals: allocation-free) ----------------
__device__ float4 g_imgs_t[NVIEW*BATCH*HWI];            // [vb][p] = (r,g,b,0)
__device__ float4 g_feats_t[NVIEW*BATCH*HWF*(CF/4)];    // [vb][p][c]

// ---------------- packed fp32x2 FMA (Blackwell FFMA2) ----------------
__device__ __forceinline__ unsigned long long ffma2(unsigned long long a,
                                                    unsigned long long b,
                                                    unsigned long long c) {
    unsigned long long d;
    asm("fma.rn.f32x2 %0, %1, %2, %3;" : "=l"(d) : "l"(a), "l"(b), "l"(c));
    return d;
}
__device__ __forceinline__ unsigned long long dup2(float x) {
    unsigned long long d;
    unsigned int xi = __float_as_uint(x);
    asm("mov.b64 %0, {%1,%1};" : "=l"(d) : "r"(xi));
    return d;
}

// ---------------- kernel 1a: transpose images [v,b,3,HW] -> [vb,HW,4] ----------------
__global__ void transpose_imgs(const float* __restrict__ im) {
    int idx = blockIdx.x * blockDim.x + threadIdx.x;   // vb*HWI + p
    if (idx >= NVIEW*BATCH*HWI) return;
    int vb = idx >> 18;
    int p  = idx & (HWI - 1);
    const float* base = im + (size_t)vb * 3 * HWI + p;
    g_imgs_t[idx] = make_float4(base[0], base[HWI], base[2*HWI], 0.f);
}

// ---------------- kernel 1b: transpose feats [v,b,32,HW] -> [vb,HW,32] ----------------
__global__ void transpose_feats(const float* __restrict__ f) {
    __shared__ float tile[32][33];
    int vb = blockIdx.y;
    int p0 = blockIdx.x * 32;
    int tx = threadIdx.x, ty = threadIdx.y;
    tile[ty][tx] = f[((size_t)vb*CF + ty) * HWF + p0 + tx];
    __syncthreads();
    ((float*)g_feats_t)[((size_t)vb*HWF + p0 + ty) * CF + tx] = tile[tx][ty];
}

// ---------------- kernel 2: FUSED gather + mean/var + MLP ----------------
// 256 threads, 64 points per block.
// Phase A (gather): 4 threads per point; thread q handles feat ch [8q,8q+8),
//   q==0 additionally the 3 img channels. Results written straight into the
//   A-tile in shared memory (no global staging).
// Phase B (GEMM): 8 warps x 8 points, 32 lanes x 4 hidden-pairs, packed f32x2
//   FMA, k unrolled by 4 with LDS.128 x-broadcasts.
#define SMEM_FLOATS (KPAD*HID + 64*KPAD + HID + HID)
#define SMEM_BYTES  (SMEM_FLOATS * 4)

__global__ __launch_bounds__(256, 2)
void fused_kernel(const float* __restrict__ grid, const float* __restrict__ pts,
                  const float* __restrict__ W1, const float* __restrict__ b1,
                  const float* __restrict__ W2, const float* __restrict__ b2,
                  float* __restrict__ out) {
    extern __shared__ float smf[];
    float* Ws  = smf;                    // [76][256]  (rows 73..75 zero)
    float* As  = smf + KPAD*HID;         // [64][76]
    float* b1s = As + 64*KPAD;           // [256]
    float* w2s = b1s + HID;              // [256]

    int tid = threadIdx.x;

    // ---- load W1 padded to 76 rows (float4), zeros in pad rows ----
    const float4* W14 = (const float4*)W1;
#pragma unroll 1
    for (int i = tid; i < KPAD*HID/4; i += 256) {
        int row = i >> 6;                // 64 float4 per row
        float4 v = make_float4(0.f, 0.f, 0.f, 0.f);
        if (row < INDIM) v = W14[i];
        ((float4*)Ws)[i] = v;
    }
    if (tid < HID) { b1s[tid] = b1[tid]; w2s[tid] = W2[tid]; }

    // ---- Phase A: gather ----
    {
        int r = tid >> 2;                // local point 0..63
        int q = tid & 3;                 // channel quarter
        int m = blockIdx.x * 64 + r;
        int b = m / NBINS;
        int n = m - b * NBINS;

        float s[11], ss[11];
#pragma unroll
        for (int c = 0; c < 11; c++) { s[c] = 0.f; ss[c] = 0.f; }

#pragma unroll
        for (int v = 0; v < NVIEW; v++) {
            float gx = grid[((size_t)v*NBINS + n)*2 + 0];
            float gy = grid[((size_t)v*NBINS + n)*2 + 1];

            // ---- feature sample: 2 c4-groups (8 channels) per quarter ----
            {
                float fx = (gx + 1.f) * 0.5f * (float)(WF - 1);
                float fy = (gy + 1.f) * 0.5f * (float)(HF - 1);
                float x0f = floorf(fx), y0f = floorf(fy);
                float wx1 = fx - x0f, wy1 = fy - y0f;
                float wx0 = 1.f - wx1, wy0 = 1.f - wy1;
                int x0 = max(0, min((int)x0f, WF-1));
                int y0 = max(0, min((int)y0f, HF-1));
                int x1 = min(x0 + 1, WF-1);
                int y1 = min(y0 + 1, HF-1);
                float w00 = wx0*wy0, w01 = wx1*wy0, w10 = wx0*wy1, w11 = wx1*wy1;
                int base = (v*BATCH + b) * HWF;
                int c4base = q * 2;
                int b00 = (base + y0*WF + x0) * (CF/4) + c4base;
                int b01 = (base + y0*WF + x1) * (CF/4) + c4base;
                int b10 = (base + y1*WF + x0) * (CF/4) + c4base;
                int b11 = (base + y1*WF + x1) * (CF/4) + c4base;
#pragma unroll
                for (int c4 = 0; c4 < 2; c4++) {
                    float4 q00 = g_feats_t[b00 + c4];
                    float4 q01 = g_feats_t[b01 + c4];
                    float4 q10 = g_feats_t[b10 + c4];
                    float4 q11 = g_feats_t[b11 + c4];
                    int c = c4*4;
                    float t;
                    t = w00*q00.x + w01*q01.x + w10*q10.x + w11*q11.x; s[c+0]+=t; ss[c+0]+=t*t;
                    t = w00*q00.y + w01*q01.y + w10*q10.y + w11*q11.y; s[c+1]+=t; ss[c+1]+=t*t;
                    t = w00*q00.z + w01*q01.z + w10*q10.z + w11*q11.z; s[c+2]+=t; ss[c+2]+=t*t;
                    t = w00*q00.w + w01*q01.w + w10*q10.w + w11*q11.w; s[c+3]+=t; ss[c+3]+=t*t;
                }
            }

            // ---- image sample (quarter 0 only) ----
            if (q == 0) {
                float fx = (gx + 1.f) * 0.5f * (float)(WI - 1);
                float fy = (gy + 1.f) * 0.5f * (float)(HI - 1);
                float x0f = floorf(fx), y0f = floorf(fy);
                float wx1 = fx - x0f, wy1 = fy - y0f;
                float wx0 = 1.f - wx1, wy0 = 1.f - wy1;
                int x0 = max(0, min((int)x0f, WI-1));
                int y0 = max(0, min((int)y0f, HI-1));
                int x1 = min(x0 + 1, WI-1);
                int y1 = min(y0 + 1, HI-1);
                float w00 = wx0*wy0, w01 = wx1*wy0, w10 = wx0*wy1, w11 = wx1*wy1;
                int base = (v*BATCH + b) * HWI;
                float4 p00 = g_imgs_t[base + y0*WI + x0];
                float4 p01 = g_imgs_t[base + y0*WI + x1];
                float4 p10 = g_imgs_t[base + y1*WI + x0];
                float4 p11 = g_imgs_t[base + y1*WI + x1];
                float r0 = w00*p00.x + w01*p01.x + w10*p10.x + w11*p11.x;
                float r1 = w00*p00.y + w01*p01.y + w10*p10.y + w11*p11.y;
                float r2 = w00*p00.z + w01*p01.z + w10*p10.z + w11*p11.z;
                s[8]  += r0; ss[8]  += r0*r0;
                s[9]  += r1; ss[9]  += r1*r1;
                s[10] += r2; ss[10] += r2*r2;
            }
        }

        // ---- finalize into As row: [pts(3), mean(35) @3, exp(-var)(35) @38, pad @73] ----
        float* o = &As[r * KPAD];
        // feat channels 8q..8q+7
#pragma unroll
        for (int c = 0; c < 8; c++) {
            float mean = s[c] * 0.2f;
            float var  = fmaxf(ss[c] * 0.2f - mean*mean, 0.f);
            o[6 + 8*q + c]  = mean;
            o[41 + 8*q + c] = expf(-var);
        }
        if (q == 0) {
            o[0] = pts[n*3 + 0];
            o[1] = pts[n*3 + 1];
            o[2] = pts[n*3 + 2];
#pragma unroll
            for (int c = 0; c < 3; c++) {
                float mean = s[8+c] * 0.2f;
                float var  = fmaxf(ss[8+c] * 0.2f - mean*mean, 0.f);
                o[3 + c]  = mean;
                o[38 + c] = expf(-var);
            }
        } else if (q == 3) {
            o[73] = 0.f; o[74] = 0.f; o[75] = 0.f;
        }
    }
    __syncthreads();

    // ---- Phase B: GEMM + epilogue ----
    int tx = tid & 31, ty = tid >> 5;    // warp ty owns points ty*8..ty*8+7
    unsigned long long acc[8][4];
#pragma unroll
    for (int mi = 0; mi < 8; mi++)
#pragma unroll
        for (int i = 0; i < 4; i++) acc[mi][i] = 0ull;

    const float* arow = &As[ty * 8 * KPAD];

#pragma unroll 1
    for (int k4 = 0; k4 < KPAD; k4 += 4) {
        float4 xv[8];
#pragma unroll
        for (int mi = 0; mi < 8; mi++)
            xv[mi] = *(const float4*)(arow + mi*KPAD + k4);   // LDS.128 broadcast
#pragma unroll
        for (int kk = 0; kk < 4; kk++) {
            unsigned long long wv[4];
            const float* wr = &Ws[(k4 + kk)*HID + tx*2];
#pragma unroll
            for (int i = 0; i < 4; i++)
                wv[i] = *(const unsigned long long*)(wr + i*64);   // LDS.64, conflict-free
#pragma unroll
            for (int mi = 0; mi < 8; mi++) {
                float xk = (kk == 0) ? xv[mi].x : (kk == 1) ? xv[mi].y
                         : (kk == 2) ? xv[mi].z : xv[mi].w;
                unsigned long long xp = dup2(xk);
#pragma unroll
                for (int i = 0; i < 4; i++)
                    acc[mi][i] = ffma2(xp, wv[i], acc[mi][i]);
            }
        }
    }

    // epilogue: relu + W2 dot + full-warp reduce + sigmoid
    float b2v = b2[0];
#pragma unroll
    for (int mi = 0; mi < 8; mi++) {
        float z = 0.f;
#pragma unroll
        for (int i = 0; i < 4; i++) {
            int j0 = i*64 + tx*2;
            float a0 = __uint_as_float((unsigned int)(acc[mi][i] & 0xffffffffull));
            float a1 = __uint_as_float((unsigned int)(acc[mi][i] >> 32));
            float h0 = fmaxf(a0 + b1s[j0],     0.f);
            float h1 = fmaxf(a1 + b1s[j0 + 1], 0.f);
            z += h0 * w2s[j0] + h1 * w2s[j0 + 1];
        }
#pragma unroll
        for (int off = 16; off >= 1; off >>= 1)
            z += __shfl_xor_sync(0xffffffffu, z, off);
        if (tx == 0) {
            float zz = z + b2v;
            // 1 - exp(-softplus(zz)) == sigmoid(zz)
            out[blockIdx.x*64 + ty*8 + mi] = 1.f / (1.f + expf(-zz));
        }
    }
}

// ---------------- launch ----------------
extern "C" void kernel_launch(void* const* d_in, const int* in_sizes, int n_in,
                              void* d_out, int out_size) {
    const float* imgs  = (const float*)d_in[0];
    const float* feats = (const float*)d_in[1];
    const float* grid  = (const float*)d_in[2];
    const float* pts   = (const float*)d_in[3];
    const float* W1    = (const float*)d_in[4];
    const float* b1    = (const float*)d_in[5];
    const float* W2    = (const float*)d_in[6];
    const float* b2    = (const float*)d_in[7];
    float* out = (float*)d_out;

    cudaFuncSetAttribute(fused_kernel, cudaFuncAttributeMaxDynamicSharedMemorySize, SMEM_BYTES);

    transpose_imgs<<<(NVIEW*BATCH*HWI + 255)/256, 256>>>(imgs);
    transpose_feats<<<dim3(HWF/32, NVIEW*BATCH), dim3(32, 32)>>>(feats);
    fused_kernel<<<MTOT/64, 256, SMEM_BYTES>>>(grid, pts, W1, b1, W2, b2, out);
}